// round 5
// baseline (speedup 1.0000x reference)
#include <cuda_runtime.h>
#include <cuda_bf16.h>

// FocalLoss (RetinaNet-style) on GB300.
// Inputs (metadata order):
//   d_in[0] classifications [B,N,C] f32
//   d_in[1] regressions     [B,N,3] f32
//   d_in[2] anchors         [B,N,3] f32  (only image 0 used, per reference)
//   d_in[3] annotations     [B,K,4] f32  (x, y, alpha, class)
// Output: float[3] = [mean cls loss, mean xy loss, mean angle loss] over B.

#define THREADS 256
#define AITEMS  4
#define TILE    (THREADS * AITEMS)
#define MAXB    8
#define MAXBLK  2048
#define MAXK    64

// Fixed-slot partials: [image][block][4] = {cls_sum, xy_sum, ang_sum, num_pos}
// Every (b, blk<gb) slot is written every launch -> no zeroing, deterministic.
__device__ float g_part[MAXB * MAXBLK * 4];

__global__ __launch_bounds__(THREADS) void focal_main(
    const float* __restrict__ cls,
    const float* __restrict__ reg,
    const float* __restrict__ anch0,   // anchors image 0 base
    const float* __restrict__ ann,
    int N, int K, int gb)
{
    const int b   = blockIdx.y;
    const int tid = threadIdx.x;

    __shared__ float sx[MAXK], sy[MAXK], sa[MAXK], scl[MAXK];
    if (tid < K) {
        const float* a = ann + ((long long)b * K + tid) * 4;
        sx[tid]  = a[0];
        sy[tid]  = a[1];
        sa[tid]  = a[2];
        scl[tid] = a[3];
    }
    __syncthreads();

    const float* clsb = cls + (long long)b * N * 4;
    const float* regb = reg + (long long)b * N * 3;

    float cls_sum = 0.f, xy_sum = 0.f, ang_sum = 0.f, npos = 0.f;

    for (int base = blockIdx.x * TILE; base < N; base += gb * TILE) {
        int      n [AITEMS];
        float    ax[AITEMS], ay[AITEMS], aal[AITEMS];
        unsigned best[AITEMS];

        #pragma unroll
        for (int j = 0; j < AITEMS; j++) {
            n[j] = base + tid + j * THREADS;
            bool v = (n[j] < N);
            long long idx = v ? (long long)n[j] * 3 : 0;
            ax[j]  = anch0[idx + 0];
            ay[j]  = anch0[idx + 1];
            aal[j] = anch0[idx + 2];
            if (!v) { ax[j] = 3.0e18f; ay[j] = 3.0e18f; }
            best[j] = 0xFFFFFFFFu;
        }

        // Hot loop: 4 fma-pipe + 2 alu-pipe ops per (anchor, annotation).
        // Argmin packed into the low 6 mantissa bits of d2 (d2 >= 0 so uint
        // ordering is monotonic). First-min tie-break matches jnp.argmin.
        #pragma unroll 4
        for (int k = 0; k < K; k++) {
            float nx = sx[k], ny = sy[k];
            #pragma unroll
            for (int j = 0; j < AITEMS; j++) {
                float dx = ax[j] - nx;
                float dy = ay[j] - ny;
                float d2 = fmaf(dx, dx, dy * dy);
                unsigned key = (__float_as_uint(d2) & ~63u) | (unsigned)k;
                best[j] = min(best[j], key);
            }
        }

        #pragma unroll
        for (int j = 0; j < AITEMS; j++) {
            if (n[j] >= N) continue;
            int   bk  = (int)(best[j] & 63u);
            float d2m = __uint_as_float(best[j] & ~63u);   // quantized dxy_min^2
            float aa  = fabsf(aal[j] - sa[bk]);

            // dxy_min >= 45  <=> d2 >= 2025 ; dxy_min < 30 <=> d2 < 900
            bool neg = (d2m >= 2025.0f) || (aa >= 30.0f);
            bool pos = (d2m < 900.0f)   && (aa < 20.0f);

            if (neg || pos) {
                int tc = pos ? (int)scl[bk] : -1;
                float4 c4 = *reinterpret_cast<const float4*>(clsb + (long long)n[j] * 4);
                float p[4] = {c4.x, c4.y, c4.z, c4.w};
                float l = 0.f;
                #pragma unroll
                for (int c = 0; c < 4; c++) {
                    float pc = fminf(fmaxf(p[c], 1e-4f), 1.f - 1e-4f);
                    if (c == tc) {
                        float q = 1.f - pc;
                        l += 0.95f * q * q * (-__logf(pc));
                    } else {
                        l += 0.05f * pc * pc * (-__logf(1.f - pc));
                    }
                }
                cls_sum += l * 0.7f;
            }

            if (pos) {
                npos += 1.f;
                float tx = sx[bk] - ax[j];
                float ty = sy[bk] - ay[j];
                float ta = sa[bk] - aal[j];
                long long ri = (long long)n[j] * 3;
                float rx = regb[ri + 0], ry = regb[ri + 1], ra = regb[ri + 2];
                float dxv = fabsf(tx - rx);
                float dyv = fabsf(ty - ry);
                float lx = (dxv <= (1.0f / 9.0f)) ? 4.5f * dxv * dxv : dxv - (0.5f / 9.0f);
                float ly = (dyv <= (1.0f / 9.0f)) ? 4.5f * dyv * dyv : dyv - (0.5f / 9.0f);
                xy_sum  += (lx + ly) * 0.7f;
                float da = fmaxf((fabsf(ta - ra) - 10.0f) * 0.2f, 0.0f);
                ang_sum += da * 0.7f;
            }
        }
    }

    // Deterministic block reduction: warp shuffle, then warp-0 folds.
    #pragma unroll
    for (int off = 16; off > 0; off >>= 1) {
        cls_sum += __shfl_down_sync(0xffffffffu, cls_sum, off);
        xy_sum  += __shfl_down_sync(0xffffffffu, xy_sum,  off);
        ang_sum += __shfl_down_sync(0xffffffffu, ang_sum, off);
        npos    += __shfl_down_sync(0xffffffffu, npos,    off);
    }
    __shared__ float ws[THREADS / 32][4];
    int warp = tid >> 5, lane = tid & 31;
    if (lane == 0) {
        ws[warp][0] = cls_sum; ws[warp][1] = xy_sum;
        ws[warp][2] = ang_sum; ws[warp][3] = npos;
    }
    __syncthreads();
    if (tid == 0) {
        float s0 = 0.f, s1 = 0.f, s2 = 0.f, s3 = 0.f;
        #pragma unroll
        for (int w = 0; w < THREADS / 32; w++) {
            s0 += ws[w][0]; s1 += ws[w][1]; s2 += ws[w][2]; s3 += ws[w][3];
        }
        float* gp = g_part + ((long long)b * MAXBLK + blockIdx.x) * 4;
        gp[0] = s0; gp[1] = s1; gp[2] = s2; gp[3] = s3;
    }
}

__global__ void focal_final(float* __restrict__ out, int B, int gb)
{
    int warp = threadIdx.x >> 5, lane = threadIdx.x & 31;
    __shared__ float res[MAXB][4];
    if (warp < B * 4) {
        int b = warp >> 2, q = warp & 3;
        float s = 0.f;
        for (int i = lane; i < gb; i += 32)
            s += g_part[((long long)b * MAXBLK + i) * 4 + q];
        #pragma unroll
        for (int off = 16; off > 0; off >>= 1)
            s += __shfl_down_sync(0xffffffffu, s, off);
        if (lane == 0) res[b][q] = s;
    }
    __syncthreads();
    if (threadIdx.x == 0) {
        float mc = 0.f, mx = 0.f, ma = 0.f;
        for (int b = 0; b < B; b++) {
            float np    = res[b][3];
            float denom = fmaxf(np, 1.0f);
            mc += res[b][0] / denom;
            mx += (np > 0.f) ? res[b][1] / (2.0f * denom) : 0.f;
            ma += (np > 0.f) ? res[b][2] / denom          : 0.f;
        }
        float inv = 1.0f / (float)B;
        out[0] = mc * inv;
        out[1] = mx * inv;
        out[2] = ma * inv;
    }
}

extern "C" void kernel_launch(void* const* d_in, const int* in_sizes, int n_in,
                              void* d_out, int out_size)
{
    const float* cls  = (const float*)d_in[0];
    const float* reg  = (const float*)d_in[1];
    const float* anch = (const float*)d_in[2];
    const float* ann  = (const float*)d_in[3];

    const int B = 4;                               // fixed problem shape
    const int N = in_sizes[1] / (3 * B);           // 300000
    const int K = in_sizes[3] / (4 * B);           // 64

    int tiles = (N + TILE - 1) / TILE;
    int gb = tiles < MAXBLK ? tiles : MAXBLK;

    dim3 grid(gb, B);
    focal_main<<<grid, THREADS>>>(cls, reg, anch, ann, N, K, gb);
    focal_final<<<1, 512>>>((float*)d_out, B, gb);
}

// round 6
// speedup vs baseline: 1.1548x; 1.1548x over previous
#include <cuda_runtime.h>
#include <cuda_bf16.h>

// FocalLoss (RetinaNet-style) on GB300.
//   d_in[0] classifications [B,N,C=4] f32
//   d_in[1] regressions     [B,N,3]   f32
//   d_in[2] anchors         [B,N,3]   f32  (only image 0 used, per reference)
//   d_in[3] annotations     [B,K,4]   f32  (x, y, alpha, class)
// Output: float[3] = [mean cls, mean xy, mean angle] over B.

#define THREADS 256
#define AITEMS  4
#define TILE    (THREADS * AITEMS)
#define MAXB    8
#define MAXBLK  2048
#define MAXK    64

typedef unsigned long long u64;
typedef long long          ll;

// Fixed-slot partials: [image][block][4] = {cls, xy, ang, num_pos}.
__device__ float    g_part[MAXB * MAXBLK * 4];
__device__ unsigned g_tick;   // zero-init; last block resets to 0 each launch

__device__ __forceinline__ u64 pack2(float lo, float hi) {
    u64 r; asm("mov.b64 %0, {%1, %2};" : "=l"(r) : "f"(lo), "f"(hi)); return r;
}
__device__ __forceinline__ void unpack2(u64 v, float& lo, float& hi) {
    asm("mov.b64 {%0, %1}, %2;" : "=f"(lo), "=f"(hi) : "l"(v));
}
#define ADD2(d, a, b)    asm("add.rn.f32x2 %0, %1, %2;"      : "=l"(d) : "l"(a), "l"(b))
#define MUL2(d, a, b)    asm("mul.rn.f32x2 %0, %1, %2;"      : "=l"(d) : "l"(a), "l"(b))
#define FMA2(d, a, b, c) asm("fma.rn.f32x2 %0, %1, %2, %3;"  : "=l"(d) : "l"(a), "l"(b), "l"(c))

__global__ __launch_bounds__(THREADS) void focal_main(
    const float* __restrict__ cls,
    const float* __restrict__ reg,
    const float* __restrict__ anch0,
    const float* __restrict__ ann,
    float* __restrict__ out,
    int N, int K, int gb, int B)
{
    const int b   = blockIdx.y;
    const int tid = threadIdx.x;

    __shared__ float sx[MAXK], sy[MAXK], sa[MAXK], scl[MAXK];
    __shared__ u64   snx2[MAXK / 2], sny2[MAXK / 2];  // packed {-n_k, -n_{k+1}}
    if (tid < K) {
        const float* a = ann + ((ll)b * K + tid) * 4;
        sx[tid]  = a[0];
        sy[tid]  = a[1];
        sa[tid]  = a[2];
        scl[tid] = a[3];
    }
    __syncthreads();
    if (tid < K / 2) {
        snx2[tid] = pack2(-sx[2 * tid], -sx[2 * tid + 1]);
        sny2[tid] = pack2(-sy[2 * tid], -sy[2 * tid + 1]);
    }
    __syncthreads();

    const float* clsb = cls + (ll)b * N * 4;
    const float* regb = reg + (ll)b * N * 3;

    float cls_sum = 0.f, xy_sum = 0.f, ang_sum = 0.f, npos = 0.f;
    const int KP = K / 2;

    for (int base = blockIdx.x * TILE; base < N; base += gb * TILE) {
        int      n [AITEMS];
        float    ax[AITEMS], ay[AITEMS], aal[AITEMS];
        u64      axax[AITEMS], ayay[AITEMS];
        unsigned best[AITEMS];

        #pragma unroll
        for (int j = 0; j < AITEMS; j++) {
            n[j] = base + tid + j * THREADS;
            bool v = (n[j] < N);
            ll idx = v ? (ll)n[j] * 3 : 0;
            ax[j]  = anch0[idx + 0];
            ay[j]  = anch0[idx + 1];
            aal[j] = anch0[idx + 2];
            if (!v) { ax[j] = 3.0e18f; ay[j] = 3.0e18f; }
            axax[j] = pack2(ax[j], ax[j]);
            ayay[j] = pack2(ay[j], ay[j]);
            best[j] = 0xFFFFFFFFu;
        }

        // Hot loop: two annotations per packed f32x2 op.
        // Per annotation: 2 fma-pipe + 2 alu-pipe issue slots.
        // Argmin packed into low 6 mantissa bits (d2 >= 0 -> monotone uint order;
        // first-min tie-break matches jnp.argmin).
        #pragma unroll 4
        for (int p = 0; p < KP; p++) {
            u64 nnx = snx2[p];
            u64 nny = sny2[p];
            unsigned k0b = (unsigned)(2 * p);
            #pragma unroll
            for (int j = 0; j < AITEMS; j++) {
                u64 dx2, dy2, sq, d2p;
                ADD2(dx2, axax[j], nnx);
                ADD2(dy2, ayay[j], nny);
                MUL2(sq, dx2, dx2);
                FMA2(d2p, dy2, dy2, sq);
                float lo, hi; unpack2(d2p, lo, hi);
                unsigned key0 = (__float_as_uint(lo) & ~63u) | k0b;
                unsigned key1 = (__float_as_uint(hi) & ~63u) | (k0b + 1u);
                best[j] = min(best[j], min(key0, key1));
            }
        }

        #pragma unroll
        for (int j = 0; j < AITEMS; j++) {
            if (n[j] >= N) continue;
            int   bk  = (int)(best[j] & 63u);
            float d2m = __uint_as_float(best[j] & ~63u);   // quantized dxy_min^2
            float aa  = fabsf(aal[j] - sa[bk]);

            // dxy_min >= 45 <=> d2 >= 2025 ; dxy_min < 30 <=> d2 < 900
            bool neg = (d2m >= 2025.0f) || (aa >= 30.0f);
            bool pos = (d2m < 900.0f)   && (aa < 20.0f);

            if (neg || pos) {
                int tc = pos ? (int)scl[bk] : -1;
                float4 c4 = *reinterpret_cast<const float4*>(clsb + (ll)n[j] * 4);
                float p4[4] = {c4.x, c4.y, c4.z, c4.w};
                float l = 0.f;
                #pragma unroll
                for (int c = 0; c < 4; c++) {
                    float pc = fminf(fmaxf(p4[c], 1e-4f), 1.f - 1e-4f);
                    if (c == tc) {
                        float q = 1.f - pc;
                        l += 0.95f * q * q * (-__logf(pc));
                    } else {
                        l += 0.05f * pc * pc * (-__logf(1.f - pc));
                    }
                }
                cls_sum += l * 0.7f;
            }

            if (pos) {
                npos += 1.f;
                float tx = sx[bk] - ax[j];
                float ty = sy[bk] - ay[j];
                float ta = sa[bk] - aal[j];
                ll ri = (ll)n[j] * 3;
                float rx = regb[ri + 0], ry = regb[ri + 1], ra = regb[ri + 2];
                float dxv = fabsf(tx - rx);
                float dyv = fabsf(ty - ry);
                float lx = (dxv <= (1.0f / 9.0f)) ? 4.5f * dxv * dxv : dxv - (0.5f / 9.0f);
                float ly = (dyv <= (1.0f / 9.0f)) ? 4.5f * dyv * dyv : dyv - (0.5f / 9.0f);
                xy_sum  += (lx + ly) * 0.7f;
                float da = fmaxf((fabsf(ta - ra) - 10.0f) * 0.2f, 0.0f);
                ang_sum += da * 0.7f;
            }
        }
    }

    // Deterministic block reduction.
    #pragma unroll
    for (int off = 16; off > 0; off >>= 1) {
        cls_sum += __shfl_down_sync(0xffffffffu, cls_sum, off);
        xy_sum  += __shfl_down_sync(0xffffffffu, xy_sum,  off);
        ang_sum += __shfl_down_sync(0xffffffffu, ang_sum, off);
        npos    += __shfl_down_sync(0xffffffffu, npos,    off);
    }
    __shared__ float ws[THREADS / 32][4];
    const int warp = tid >> 5, lane = tid & 31;
    if (lane == 0) {
        ws[warp][0] = cls_sum; ws[warp][1] = xy_sum;
        ws[warp][2] = ang_sum; ws[warp][3] = npos;
    }
    __syncthreads();
    if (tid == 0) {
        float s0 = 0.f, s1 = 0.f, s2 = 0.f, s3 = 0.f;
        #pragma unroll
        for (int w = 0; w < THREADS / 32; w++) {
            s0 += ws[w][0]; s1 += ws[w][1]; s2 += ws[w][2]; s3 += ws[w][3];
        }
        float* gp = g_part + ((ll)b * MAXBLK + blockIdx.x) * 4;
        gp[0] = s0; gp[1] = s1; gp[2] = s2; gp[3] = s3;
    }

    // ---- fused final reduction: last block to arrive does it ----
    __threadfence();
    __shared__ bool amLast;
    if (tid == 0) {
        unsigned total = gridDim.x * gridDim.y;
        amLast = (atomicAdd(&g_tick, 1u) == total - 1u);
    }
    __syncthreads();
    if (!amLast) return;
    __threadfence();

    __shared__ float res[MAXB][4];
    // 8 warps handle B*4 (image, quantity) pairs; each lane strides partials
    // in fixed order -> deterministic.
    for (int pair = warp; pair < B * 4; pair += (THREADS / 32)) {
        int bb = pair >> 2, q = pair & 3;
        float s = 0.f;
        for (int i = lane; i < gb; i += 32)
            s += g_part[((ll)bb * MAXBLK + i) * 4 + q];
        #pragma unroll
        for (int off = 16; off > 0; off >>= 1)
            s += __shfl_down_sync(0xffffffffu, s, off);
        if (lane == 0) res[bb][q] = s;
    }
    __syncthreads();
    if (tid == 0) {
        float mc = 0.f, mx = 0.f, ma = 0.f;
        for (int bb = 0; bb < B; bb++) {
            float np    = res[bb][3];
            float denom = fmaxf(np, 1.0f);
            mc += res[bb][0] / denom;
            mx += (np > 0.f) ? res[bb][1] / (2.0f * denom) : 0.f;
            ma += (np > 0.f) ? res[bb][2] / denom          : 0.f;
        }
        float inv = 1.0f / (float)B;
        out[0] = mc * inv;
        out[1] = mx * inv;
        out[2] = ma * inv;
        g_tick = 0;   // reset for next (graph-replayed) launch
    }
}

extern "C" void kernel_launch(void* const* d_in, const int* in_sizes, int n_in,
                              void* d_out, int out_size)
{
    const float* cls  = (const float*)d_in[0];
    const float* reg  = (const float*)d_in[1];
    const float* anch = (const float*)d_in[2];
    const float* ann  = (const float*)d_in[3];

    const int B = 4;
    const int N = in_sizes[1] / (3 * B);   // 300000
    const int K = in_sizes[3] / (4 * B);   // 64

    int tiles = (N + TILE - 1) / TILE;
    int gb = tiles < MAXBLK ? tiles : MAXBLK;

    dim3 grid(gb, B);
    focal_main<<<grid, THREADS>>>(cls, reg, anch, ann, (float*)d_out, N, K, gb, B);
}